// round 13
// baseline (speedup 1.0000x reference)
#include <cuda_runtime.h>
#include <cuda_bf16.h>
#include <cstdint>
#include <cstddef>

// Problem constants
#define T_STEPS 1024
#define BATCH   64
#define DIM     512
#define HID     512
#define DH      1024          // D + H
#define G4      2048          // 4*H
#define MROWS   (T_STEPS * BATCH)   // 65536

// Phase-2 partitioning: 4 groups x 32 CTAs, 1 CTA per SM
#define NGROUPS 4
#define CPG     32
#define NCTA    128
#define BPG     16            // batches per group
#define JPC     16            // hidden units per CTA
#define KPH     520           // padded h_s row stride (floats)

// ---------------- device scratch (static allocations only) ----------------
__device__ float    g_zx[(size_t)MROWS * G4];   // precomputed x-part + bias
__device__ float    g_h[2][BATCH][HID];         // double-buffered hidden state
__device__ unsigned g_cnt[NGROUPS * 32];        // barrier counters, 128B apart

__device__ __forceinline__ unsigned ld_acq(unsigned* p) {
    unsigned v;
    asm volatile("ld.acquire.gpu.u32 %0, [%1];" : "=r"(v) : "l"(p) : "memory");
    return v;
}

// ---------------- packed fp32 helpers (FFMA2 on sm_103) ----------------
__device__ __forceinline__ void fma2(unsigned long long& d, unsigned long long a,
                                     unsigned long long b) {
    asm("fma.rn.f32x2 %0, %1, %2, %0;" : "+l"(d) : "l"(a), "l"(b));
}
__device__ __forceinline__ unsigned long long pk2(float x, float y) {
    unsigned long long r;
    asm("mov.b64 %0, {%1, %2};" : "=l"(r) : "f"(x), "f"(y));
    return r;
}
__device__ __forceinline__ float2 unpk(unsigned long long v) {
    float2 r;
    asm("mov.b64 {%0, %1}, %2;" : "=f"(r.x), "=f"(r.y) : "l"(v));
    return r;
}

// ---------------- fast transcendentals (|.|-guarded, err ~1e-6) ----------------
__device__ __forceinline__ float fsig(float z) {
    float e = __expf(-fabsf(z));
    float r = __fdividef(1.f, 1.f + e);
    return z >= 0.f ? r : 1.f - r;
}
__device__ __forceinline__ float ftanh(float z) {
    float e = __expf(-2.f * fabsf(z));
    float r = __fdividef(1.f - e, 1.f + e);
    return copysignf(r, z);
}

// ---------------- cp.async helpers ----------------
__device__ __forceinline__ uint32_t smem_u32(const void* p) {
    uint32_t a;
    asm("{ .reg .u64 t; cvta.to.shared.u64 t, %1; cvt.u32.u64 %0, t; }" : "=r"(a) : "l"(p));
    return a;
}
__device__ __forceinline__ void cp16(uint32_t dst, const void* src) {
    asm volatile("cp.async.cg.shared.global [%0], [%1], 16;" :: "r"(dst), "l"(src));
}
__device__ __forceinline__ void cp_commit() { asm volatile("cp.async.commit_group;" ::: "memory"); }
__device__ __forceinline__ void cp_wait0() {
    asm volatile("cp.async.wait_group 0;" ::: "memory");
}

// =======================================================================
// Phase 1: fp32x2 SGEMM (R6/R7 version verbatim — measured 2.43 ms).
// =======================================================================
#define KPAD 132
__global__ __launch_bounds__(256, 2) void p1_gemm(
    const float* __restrict__ X,
    const float* __restrict__ Wf, const float* __restrict__ Wi,
    const float* __restrict__ Wg, const float* __restrict__ Wo,
    const float* __restrict__ bf, const float* __restrict__ bi,
    const float* __restrict__ bg, const float* __restrict__ bo)
{
    __shared__ float As[16][KPAD];
    __shared__ float Bs[16][KPAD];

    const int tid = threadIdx.x;
    const int m0  = blockIdx.y * 128;
    const int n0  = blockIdx.x * 128;
    const int gate = n0 >> 9;
    const float* Wsel = (gate == 0) ? Wf : (gate == 1) ? Wi : (gate == 2) ? Wg : Wo;
    const float* bsel = (gate == 0) ? bf : (gate == 1) ? bi : (gate == 2) ? bg : bo;
    const int jbase = n0 & 511;

    const int tm = tid & 15;
    const int tn = tid >> 4;
    const int lrow = tid >> 2, lkc = tid & 3;

    unsigned long long acc2[4][8];
#pragma unroll
    for (int i = 0; i < 4; i++)
#pragma unroll
        for (int q = 0; q < 8; q++) acc2[i][q] = 0ull;

    float4 ra[2], rb[2];
    auto ldg_tile = [&](int k0) {
#pragma unroll
        for (int l = 0; l < 2; l++) {
            int row = lrow + l * 64;
            ra[l] = *(const float4*)&X[(size_t)(m0 + row) * 512 + k0 + lkc * 4];
            rb[l] = *(const float4*)&Wsel[(size_t)(jbase + row) * DH + k0 + lkc * 4];
        }
    };
    auto sts_tile = [&]() {
#pragma unroll
        for (int l = 0; l < 2; l++) {
            int row = lrow + l * 64;
            As[lkc * 4 + 0][row] = ra[l].x;
            As[lkc * 4 + 1][row] = ra[l].y;
            As[lkc * 4 + 2][row] = ra[l].z;
            As[lkc * 4 + 3][row] = ra[l].w;
            Bs[lkc * 4 + 0][row] = rb[l].x;
            Bs[lkc * 4 + 1][row] = rb[l].y;
            Bs[lkc * 4 + 2][row] = rb[l].z;
            Bs[lkc * 4 + 3][row] = rb[l].w;
        }
    };

    ldg_tile(0);
    for (int k0 = 0; k0 < 512; k0 += 16) {
        sts_tile();
        __syncthreads();
        if (k0 + 16 < 512) ldg_tile(k0 + 16);

#pragma unroll
        for (int k = 0; k < 16; k++) {
            unsigned long long a2[4];
#pragma unroll
            for (int p = 0; p < 4; p++)
                a2[p] = *(const unsigned long long*)&As[k][32 * p + 2 * tm];
            float4 bv0 = *(const float4*)&Bs[k][tn * 8];
            float4 bv1 = *(const float4*)&Bs[k][tn * 8 + 4];
            unsigned long long b2[8];
            b2[0] = pk2(bv0.x, bv0.x); b2[1] = pk2(bv0.y, bv0.y);
            b2[2] = pk2(bv0.z, bv0.z); b2[3] = pk2(bv0.w, bv0.w);
            b2[4] = pk2(bv1.x, bv1.x); b2[5] = pk2(bv1.y, bv1.y);
            b2[6] = pk2(bv1.z, bv1.z); b2[7] = pk2(bv1.w, bv1.w);
#pragma unroll
            for (int p = 0; p < 4; p++)
#pragma unroll
                for (int q = 0; q < 8; q++) fma2(acc2[p][q], a2[p], b2[q]);
        }
        __syncthreads();
    }

    float bias[8];
#pragma unroll
    for (int q = 0; q < 8; q++) bias[q] = bsel[jbase + tn * 8 + q];

#pragma unroll
    for (int p = 0; p < 4; p++) {
        const int mrow = m0 + 32 * p + 2 * tm;
        float lo[8], hi[8];
#pragma unroll
        for (int q = 0; q < 8; q++) {
            float2 v = unpk(acc2[p][q]);
            lo[q] = v.x + bias[q];
            hi[q] = v.y + bias[q];
        }
        float* r0 = &g_zx[(size_t)mrow * G4 + n0 + tn * 8];
        float* r1 = r0 + G4;
        *(float4*)r0       = make_float4(lo[0], lo[1], lo[2], lo[3]);
        *(float4*)(r0 + 4) = make_float4(lo[4], lo[5], lo[6], lo[7]);
        *(float4*)r1       = make_float4(hi[0], hi[1], hi[2], hi[3]);
        *(float4*)(r1 + 4) = make_float4(hi[4], hi[5], hi[6], hi[7]);
    }
}

// =======================================================================
// Reset kernel
// =======================================================================
__global__ void reset_k()
{
    int tid = threadIdx.x;
    if (tid < NGROUPS * 32) g_cnt[tid] = 0;
    float* p = &g_h[0][0][0];
    for (int i = tid; i < BATCH * HID; i += 256) p[i] = 0.f;
}

// =======================================================================
// Phase 2: persistent sequential LSTM (R5/R11 structure; barrier wait
// moved AFTER the independent zx prefetch so DRAM latency hides inside
// the barrier-propagation window).
// =======================================================================
#define SMEM2 ((32768 + 16 * KPH + 8192) * 4)

__global__ __launch_bounds__(256, 1) void lstm_seq(
    const float* __restrict__ Wf, const float* __restrict__ Wi,
    const float* __restrict__ Wg, const float* __restrict__ Wo,
    const float* __restrict__ q_scale, const float* __restrict__ q_bias,
    float* __restrict__ out)
{
    extern __shared__ float smf[];
    float* wp_s = smf;                                   // 32768 floats (128KB)
    float* h_s  = smf + 32768;                           // 16*KPH
    unsigned long long* red2 = (unsigned long long*)(smf + 32768 + 16 * KPH); // 4096 u64

    const int tid = threadIdx.x;
    const int cta = blockIdx.x;
    const int grp = cta >> 5;
    const int cig = cta & 31;
    const int b0  = grp * BPG;
    const int j0  = cig * JPC;

    // Load recurrent weights (columns [512,1024)) into paired+swizzled layout.
    for (int idx = tid; idx < 64 * 512; idx += 256) {
        int rr = idx >> 9, k = idx & 511;
        int gate = rr >> 4, jl_ = rr & 15;
        const float* wpt = (gate == 0) ? Wf : (gate == 1) ? Wi : (gate == 2) ? Wg : Wo;
        float v = wpt[(size_t)(j0 + jl_) * DH + 512 + k];
        int p = rr >> 1, half = rr & 1, g = k >> 1, ko = k & 1;
        wp_s[p * 1024 + ((g ^ (p & 7)) << 2) + ko * 2 + half] = v;
    }

    const int jl = tid & 15, bl = tid >> 4;
    const int j = j0 + jl, b = b0 + bl;
    const float qs = q_scale[j], qb = q_bias[j];

    const int lane = tid & 31, wrp = tid >> 5;
    const int rL = lane & 7, bL = lane >> 3;
    const int kbase = wrp * 64;
    const int uB = bl >> 2, bLL = bl & 3;
    const float* wthr = wp_s + rL * 1024;
    float* redf = (float*)red2;
    const uint32_t hs_base = smem_u32(h_s);
    unsigned* cntp = &g_cnt[grp * 32];

    float creg = 0.f;
    __syncthreads();

    for (int t = 0; t < T_STEPS; t++) {
        // ---- prefetch Zx FIRST: independent of group barrier (DRAM fetch
        //      overlaps the barrier wait below) ----
        const float* zxp = &g_zx[((size_t)(t * BATCH + b)) * G4 + j];
        float zpre[4];
#pragma unroll
        for (int gate = 0; gate < 4; gate++) zpre[gate] = __ldcg(zxp + gate * 512);

        // ---- group barrier: h_t from all CTAs in group must be visible ----
        if (t > 0) {
            if (tid == 0) {
                const unsigned target = (unsigned)t * CPG;
                while (ld_acq(cntp) < target) { }
            }
            __syncthreads();
        }

        // ---- stage h_t for this group's 16 batches (L2 -> smem, cp.async) ----
        const float* hsrc = &g_h[t & 1][b0][0];
#pragma unroll
        for (int l = 0; l < 8; l++) {
            int i = tid + l * 256;
            int row = i >> 7, c4 = i & 127;
            cp16(hs_base + (uint32_t)(row * KPH + c4 * 4) * 4u, hsrc + row * 512 + c4 * 4);
        }
        cp_commit();
        cp_wait0();
        __syncthreads();

        // ---- packed GEMM: warp owns K-chunk of 64; 16 batch x 8 row-pairs ----
        unsigned long long acc2[4][4];
#pragma unroll
        for (int u = 0; u < 4; u++)
#pragma unroll
            for (int jj = 0; jj < 4; jj++) acc2[u][jj] = 0ull;

#pragma unroll 4
        for (int kk = 0; kk < 64; kk += 4) {
            const int k = kbase + kk;
            const int g0 = k >> 1;                       // even
            const int s0 = ((g0 ^ rL) << 2);
            const int s1 = (((g0 + 1) ^ rL) << 2);

            unsigned long long hp[4][4];
#pragma unroll
            for (int u = 0; u < 4; u++) {
                float4 hv = *(const float4*)&h_s[(bL + 4 * u) * KPH + k];
                hp[u][0] = pk2(hv.x, hv.x);
                hp[u][1] = pk2(hv.y, hv.y);
                hp[u][2] = pk2(hv.z, hv.z);
                hp[u][3] = pk2(hv.w, hv.w);
            }
#pragma unroll
            for (int jj = 0; jj < 4; jj++) {
                const float* wj = wthr + jj * 8192;
                ulonglong2 wA = *(const ulonglong2*)(wj + s0);   // k, k+1
                ulonglong2 wB = *(const ulonglong2*)(wj + s1);   // k+2, k+3
#pragma unroll
                for (int u = 0; u < 4; u++) {
                    fma2(acc2[u][jj], hp[u][0], wA.x);
                    fma2(acc2[u][jj], hp[u][1], wA.y);
                    fma2(acc2[u][jj], hp[u][2], wB.x);
                    fma2(acc2[u][jj], hp[u][3], wB.y);
                }
            }
        }

        // ---- write packed partials ----
#pragma unroll
        for (int u = 0; u < 4; u++)
#pragma unroll
            for (int jj = 0; jj < 4; jj++)
                red2[wrp * 512 + (u * 4 + jj) * 32 + rL * 4 + bL] = acc2[u][jj];
        __syncthreads();

        // ---- reduce across 8 warps, add Zx, gates, state update ----
        float z[4];
#pragma unroll
        for (int gate = 0; gate < 4; gate++) {
            int r = gate * 16 + jl;
            int p = r >> 1;
            int idx = ((uB * 4 + (p >> 3)) * 32 + (p & 7) * 4 + bLL) * 2 + (r & 1);
            float s = 0.f;
#pragma unroll
            for (int ww = 0; ww < 8; ww++) s += redf[ww * 1024 + idx];
            z[gate] = s + zpre[gate];
        }

        float fg = ftanh(fsig(z[0]) * qs + qb);
        float ig = ftanh(fsig(z[1]) * qs + qb);
        float gg = ftanh(ftanh(z[2]) * qs + qb);
        float og = ftanh(fsig(z[3]) * qs + qb);

        float c = fg * creg + ig * gg;
        creg = c;
        float h = og * ftanh(c);

        g_h[(t + 1) & 1][b][j] = h;
        __syncthreads();              // all h stores done CTA-wide

        // arrive (signal h_{t+1} ready); out[] stores overlap propagation
        if (t < T_STEPS - 1 && tid == 0) {
            __threadfence();
            atomicAdd(cntp, 1u);
        }

        out[(size_t)t * (BATCH * HID) + b * HID + j] = h;
        if (t == T_STEPS - 1) {
            out[(size_t)T_STEPS * (BATCH * HID) + b * HID + j] = h;                 // hx
            out[(size_t)T_STEPS * (BATCH * HID) + BATCH * HID + b * HID + j] = c;   // cx
        }
    }
}

// =======================================================================
// Launch (sequential, single stream)
// =======================================================================
extern "C" void kernel_launch(void* const* d_in, const int* in_sizes, int n_in,
                              void* d_out, int out_size)
{
    const float* X  = (const float*)d_in[0];
    const float* Wf = (const float*)d_in[1];
    const float* bf = (const float*)d_in[2];
    const float* Wi = (const float*)d_in[3];
    const float* bi = (const float*)d_in[4];
    const float* Wg = (const float*)d_in[5];
    const float* bg = (const float*)d_in[6];
    const float* Wo = (const float*)d_in[7];
    const float* bo = (const float*)d_in[8];
    const float* qs = (const float*)d_in[9];
    const float* qb = (const float*)d_in[10];
    float* out = (float*)d_out;

    cudaFuncSetAttribute(lstm_seq, cudaFuncAttributeMaxDynamicSharedMemorySize, SMEM2);

    p1_gemm<<<dim3(G4 / 128, MROWS / 128), 256>>>(X, Wf, Wi, Wg, Wo, bf, bi, bg, bo);
    reset_k<<<1, 256>>>();
    lstm_seq<<<NCTA, 256, SMEM2>>>(Wf, Wi, Wg, Wo, qs, qb, out);
}

// round 14
// speedup vs baseline: 1.6005x; 1.6005x over previous
#include <cuda_runtime.h>
#include <cuda_bf16.h>
#include <cstdint>
#include <cstddef>

// Problem constants
#define T_STEPS 1024
#define BATCH   64
#define DIM     512
#define HID     512
#define DH      1024          // D + H
#define G4      2048          // 4*H
#define MROWS   (T_STEPS * BATCH)   // 65536

// Phase-2 partitioning: 4 groups x 32 CTAs, 1 CTA per SM
#define NGROUPS 4
#define CPG     32
#define NCTA    128
#define BPG     16            // batches per group
#define JPC     16            // hidden units per CTA
#define KPH     520           // padded h_s row stride (floats)

// ---------------- device scratch (static allocations only) ----------------
__device__ float    g_zx[(size_t)MROWS * G4];   // precomputed x-part + bias
__device__ float    g_h[2][BATCH][HID];         // double-buffered hidden state
__device__ unsigned g_cnt[NGROUPS * 32];        // barrier counters, 128B apart

__device__ __forceinline__ unsigned ld_acq(unsigned* p) {
    unsigned v;
    asm volatile("ld.acquire.gpu.u32 %0, [%1];" : "=r"(v) : "l"(p) : "memory");
    return v;
}

// ---------------- packed fp32 helpers (FFMA2 on sm_103) ----------------
__device__ __forceinline__ void fma2(unsigned long long& d, unsigned long long a,
                                     unsigned long long b) {
    asm("fma.rn.f32x2 %0, %1, %2, %0;" : "+l"(d) : "l"(a), "l"(b));
}
__device__ __forceinline__ unsigned long long pk2(float x, float y) {
    unsigned long long r;
    asm("mov.b64 %0, {%1, %2};" : "=l"(r) : "f"(x), "f"(y));
    return r;
}
__device__ __forceinline__ float2 unpk(unsigned long long v) {
    float2 r;
    asm("mov.b64 {%0, %1}, %2;" : "=f"(r.x), "=f"(r.y) : "l"(v));
    return r;
}

// ---------------- fast transcendentals (|.|-guarded, err ~1e-6) ----------------
__device__ __forceinline__ float fsig(float z) {
    float e = __expf(-fabsf(z));
    float r = __fdividef(1.f, 1.f + e);
    return z >= 0.f ? r : 1.f - r;
}
__device__ __forceinline__ float ftanh(float z) {
    float e = __expf(-2.f * fabsf(z));
    float r = __fdividef(1.f - e, 1.f + e);
    return copysignf(r, z);
}

// ---------------- cp.async helpers ----------------
__device__ __forceinline__ uint32_t smem_u32(const void* p) {
    uint32_t a;
    asm("{ .reg .u64 t; cvta.to.shared.u64 t, %1; cvt.u32.u64 %0, t; }" : "=r"(a) : "l"(p));
    return a;
}
__device__ __forceinline__ void cp16(uint32_t dst, const void* src) {
    asm volatile("cp.async.cg.shared.global [%0], [%1], 16;" :: "r"(dst), "l"(src));
}
__device__ __forceinline__ void cp_commit() { asm volatile("cp.async.commit_group;" ::: "memory"); }
__device__ __forceinline__ void cp_wait0() {
    asm volatile("cp.async.wait_group 0;" ::: "memory");
}

// =======================================================================
// Phase 1: fp32x2 SGEMM (R6/R7 version verbatim — measured 2.43 ms).
// =======================================================================
#define KPAD 132
__global__ __launch_bounds__(256, 2) void p1_gemm(
    const float* __restrict__ X,
    const float* __restrict__ Wf, const float* __restrict__ Wi,
    const float* __restrict__ Wg, const float* __restrict__ Wo,
    const float* __restrict__ bf, const float* __restrict__ bi,
    const float* __restrict__ bg, const float* __restrict__ bo)
{
    __shared__ float As[16][KPAD];
    __shared__ float Bs[16][KPAD];

    const int tid = threadIdx.x;
    const int m0  = blockIdx.y * 128;
    const int n0  = blockIdx.x * 128;
    const int gate = n0 >> 9;
    const float* Wsel = (gate == 0) ? Wf : (gate == 1) ? Wi : (gate == 2) ? Wg : Wo;
    const float* bsel = (gate == 0) ? bf : (gate == 1) ? bi : (gate == 2) ? bg : bo;
    const int jbase = n0 & 511;

    const int tm = tid & 15;
    const int tn = tid >> 4;
    const int lrow = tid >> 2, lkc = tid & 3;

    unsigned long long acc2[4][8];
#pragma unroll
    for (int i = 0; i < 4; i++)
#pragma unroll
        for (int q = 0; q < 8; q++) acc2[i][q] = 0ull;

    float4 ra[2], rb[2];
    auto ldg_tile = [&](int k0) {
#pragma unroll
        for (int l = 0; l < 2; l++) {
            int row = lrow + l * 64;
            ra[l] = *(const float4*)&X[(size_t)(m0 + row) * 512 + k0 + lkc * 4];
            rb[l] = *(const float4*)&Wsel[(size_t)(jbase + row) * DH + k0 + lkc * 4];
        }
    };
    auto sts_tile = [&]() {
#pragma unroll
        for (int l = 0; l < 2; l++) {
            int row = lrow + l * 64;
            As[lkc * 4 + 0][row] = ra[l].x;
            As[lkc * 4 + 1][row] = ra[l].y;
            As[lkc * 4 + 2][row] = ra[l].z;
            As[lkc * 4 + 3][row] = ra[l].w;
            Bs[lkc * 4 + 0][row] = rb[l].x;
            Bs[lkc * 4 + 1][row] = rb[l].y;
            Bs[lkc * 4 + 2][row] = rb[l].z;
            Bs[lkc * 4 + 3][row] = rb[l].w;
        }
    };

    ldg_tile(0);
    for (int k0 = 0; k0 < 512; k0 += 16) {
        sts_tile();
        __syncthreads();
        if (k0 + 16 < 512) ldg_tile(k0 + 16);

#pragma unroll
        for (int k = 0; k < 16; k++) {
            unsigned long long a2[4];
#pragma unroll
            for (int p = 0; p < 4; p++)
                a2[p] = *(const unsigned long long*)&As[k][32 * p + 2 * tm];
            float4 bv0 = *(const float4*)&Bs[k][tn * 8];
            float4 bv1 = *(const float4*)&Bs[k][tn * 8 + 4];
            unsigned long long b2[8];
            b2[0] = pk2(bv0.x, bv0.x); b2[1] = pk2(bv0.y, bv0.y);
            b2[2] = pk2(bv0.z, bv0.z); b2[3] = pk2(bv0.w, bv0.w);
            b2[4] = pk2(bv1.x, bv1.x); b2[5] = pk2(bv1.y, bv1.y);
            b2[6] = pk2(bv1.z, bv1.z); b2[7] = pk2(bv1.w, bv1.w);
#pragma unroll
            for (int p = 0; p < 4; p++)
#pragma unroll
                for (int q = 0; q < 8; q++) fma2(acc2[p][q], a2[p], b2[q]);
        }
        __syncthreads();
    }

    float bias[8];
#pragma unroll
    for (int q = 0; q < 8; q++) bias[q] = bsel[jbase + tn * 8 + q];

#pragma unroll
    for (int p = 0; p < 4; p++) {
        const int mrow = m0 + 32 * p + 2 * tm;
        float lo[8], hi[8];
#pragma unroll
        for (int q = 0; q < 8; q++) {
            float2 v = unpk(acc2[p][q]);
            lo[q] = v.x + bias[q];
            hi[q] = v.y + bias[q];
        }
        float* r0 = &g_zx[(size_t)mrow * G4 + n0 + tn * 8];
        float* r1 = r0 + G4;
        *(float4*)r0       = make_float4(lo[0], lo[1], lo[2], lo[3]);
        *(float4*)(r0 + 4) = make_float4(lo[4], lo[5], lo[6], lo[7]);
        *(float4*)r1       = make_float4(hi[0], hi[1], hi[2], hi[3]);
        *(float4*)(r1 + 4) = make_float4(hi[4], hi[5], hi[6], hi[7]);
    }
}

// =======================================================================
// Reset kernel
// =======================================================================
__global__ void reset_k()
{
    int tid = threadIdx.x;
    if (tid < NGROUPS * 32) g_cnt[tid] = 0;
    float* p = &g_h[0][0][0];
    for (int i = tid; i < BATCH * HID; i += 256) p[i] = 0.f;
}

// =======================================================================
// Phase 2: persistent sequential LSTM — R11 verbatim EXCEPT the zx
// prefetch for step t+1 is hoisted before the end-of-loop barrier wait
// (independent of peers' h; DRAM fetch hides under barrier propagation).
// =======================================================================
#define SMEM2 ((32768 + 16 * KPH + 8192) * 4)

__global__ __launch_bounds__(256, 1) void lstm_seq(
    const float* __restrict__ Wf, const float* __restrict__ Wi,
    const float* __restrict__ Wg, const float* __restrict__ Wo,
    const float* __restrict__ q_scale, const float* __restrict__ q_bias,
    float* __restrict__ out)
{
    extern __shared__ float smf[];
    float* wp_s = smf;                                   // 32768 floats (128KB)
    float* h_s  = smf + 32768;                           // 16*KPH
    unsigned long long* red2 = (unsigned long long*)(smf + 32768 + 16 * KPH); // 4096 u64

    const int tid = threadIdx.x;
    const int cta = blockIdx.x;
    const int grp = cta >> 5;
    const int cig = cta & 31;
    const int b0  = grp * BPG;
    const int j0  = cig * JPC;

    // Load recurrent weights (columns [512,1024)) into paired+swizzled layout.
    for (int idx = tid; idx < 64 * 512; idx += 256) {
        int rr = idx >> 9, k = idx & 511;
        int gate = rr >> 4, jl_ = rr & 15;
        const float* wpt = (gate == 0) ? Wf : (gate == 1) ? Wi : (gate == 2) ? Wg : Wo;
        float v = wpt[(size_t)(j0 + jl_) * DH + 512 + k];
        int p = rr >> 1, half = rr & 1, g = k >> 1, ko = k & 1;
        wp_s[p * 1024 + ((g ^ (p & 7)) << 2) + ko * 2 + half] = v;
    }

    const int jl = tid & 15, bl = tid >> 4;
    const int j = j0 + jl, b = b0 + bl;
    const float qs = q_scale[j], qb = q_bias[j];

    const int lane = tid & 31, wrp = tid >> 5;
    const int rL = lane & 7, bL = lane >> 3;
    const int kbase = wrp * 64;
    const int uB = bl >> 2, bLL = bl & 3;
    const float* wthr = wp_s + rL * 1024;
    float* redf = (float*)red2;
    const uint32_t hs_base = smem_u32(h_s);
    unsigned* cntp = &g_cnt[grp * 32];

    float creg = 0.f;
    __syncthreads();

    // prefetch zx for step 0
    float zpre[4];
    {
        const float* zxp = &g_zx[((size_t)b) * G4 + j];
#pragma unroll
        for (int gate = 0; gate < 4; gate++) zpre[gate] = __ldcg(zxp + gate * 512);
    }

    for (int t = 0; t < T_STEPS; t++) {
        // ---- stage h_t for this group's 16 batches (L2 -> smem, cp.async) ----
        const float* hsrc = &g_h[t & 1][b0][0];
#pragma unroll
        for (int l = 0; l < 8; l++) {
            int i = tid + l * 256;
            int row = i >> 7, c4 = i & 127;
            cp16(hs_base + (uint32_t)(row * KPH + c4 * 4) * 4u, hsrc + row * 512 + c4 * 4);
        }
        cp_commit();
        cp_wait0();
        __syncthreads();

        // ---- packed GEMM: warp owns K-chunk of 64; 16 batch x 8 row-pairs ----
        unsigned long long acc2[4][4];
#pragma unroll
        for (int u = 0; u < 4; u++)
#pragma unroll
            for (int jj = 0; jj < 4; jj++) acc2[u][jj] = 0ull;

#pragma unroll 4
        for (int kk = 0; kk < 64; kk += 4) {
            const int k = kbase + kk;
            const int g0 = k >> 1;                       // even
            const int s0 = ((g0 ^ rL) << 2);
            const int s1 = (((g0 + 1) ^ rL) << 2);

            unsigned long long hp[4][4];
#pragma unroll
            for (int u = 0; u < 4; u++) {
                float4 hv = *(const float4*)&h_s[(bL + 4 * u) * KPH + k];
                hp[u][0] = pk2(hv.x, hv.x);
                hp[u][1] = pk2(hv.y, hv.y);
                hp[u][2] = pk2(hv.z, hv.z);
                hp[u][3] = pk2(hv.w, hv.w);
            }
#pragma unroll
            for (int jj = 0; jj < 4; jj++) {
                const float* wj = wthr + jj * 8192;
                ulonglong2 wA = *(const ulonglong2*)(wj + s0);   // k, k+1
                ulonglong2 wB = *(const ulonglong2*)(wj + s1);   // k+2, k+3
#pragma unroll
                for (int u = 0; u < 4; u++) {
                    fma2(acc2[u][jj], hp[u][0], wA.x);
                    fma2(acc2[u][jj], hp[u][1], wA.y);
                    fma2(acc2[u][jj], hp[u][2], wB.x);
                    fma2(acc2[u][jj], hp[u][3], wB.y);
                }
            }
        }

        // ---- write packed partials ----
#pragma unroll
        for (int u = 0; u < 4; u++)
#pragma unroll
            for (int jj = 0; jj < 4; jj++)
                red2[wrp * 512 + (u * 4 + jj) * 32 + rL * 4 + bL] = acc2[u][jj];
        __syncthreads();

        // ---- reduce across 8 warps, add Zx, gates, state update ----
        float z[4];
#pragma unroll
        for (int gate = 0; gate < 4; gate++) {
            int r = gate * 16 + jl;
            int p = r >> 1;
            int idx = ((uB * 4 + (p >> 3)) * 32 + (p & 7) * 4 + bLL) * 2 + (r & 1);
            float s = 0.f;
#pragma unroll
            for (int ww = 0; ww < 8; ww++) s += redf[ww * 1024 + idx];
            z[gate] = s + zpre[gate];
        }

        float fg = ftanh(fsig(z[0]) * qs + qb);
        float ig = ftanh(fsig(z[1]) * qs + qb);
        float gg = ftanh(ftanh(z[2]) * qs + qb);
        float og = ftanh(fsig(z[3]) * qs + qb);

        float c = fg * creg + ig * gg;
        creg = c;
        float h = og * ftanh(c);

        g_h[(t + 1) & 1][b][j] = h;
        __syncthreads();              // all h stores done CTA-wide

        // arrive early: overlap out[] stores with peers' arrivals
        if (t < T_STEPS - 1 && tid == 0) {
            __threadfence();
            atomicAdd(cntp, 1u);
        }

        out[(size_t)t * (BATCH * HID) + b * HID + j] = h;
        if (t == T_STEPS - 1) {
            out[(size_t)T_STEPS * (BATCH * HID) + b * HID + j] = h;                 // hx
            out[(size_t)T_STEPS * (BATCH * HID) + BATCH * HID + b * HID + j] = c;   // cx
        }

        if (t < T_STEPS - 1) {
            // prefetch zx for step t+1 BEFORE the barrier wait (independent
            // of peers' h; DRAM latency hides under barrier propagation)
            const float* zxn = &g_zx[((size_t)((t + 1) * BATCH + b)) * G4 + j];
#pragma unroll
            for (int gate = 0; gate < 4; gate++) zpre[gate] = __ldcg(zxn + gate * 512);

            if (tid == 0) {
                const unsigned target = (unsigned)(t + 1) * CPG;
                while (ld_acq(cntp) < target) { __nanosleep(16); }
            }
            __syncthreads();
        }
    }
}

// =======================================================================
// Launch (sequential, single stream)
// =======================================================================
extern "C" void kernel_launch(void* const* d_in, const int* in_sizes, int n_in,
                              void* d_out, int out_size)
{
    const float* X  = (const float*)d_in[0];
    const float* Wf = (const float*)d_in[1];
    const float* bf = (const float*)d_in[2];
    const float* Wi = (const float*)d_in[3];
    const float* bi = (const float*)d_in[4];
    const float* Wg = (const float*)d_in[5];
    const float* bg = (const float*)d_in[6];
    const float* Wo = (const float*)d_in[7];
    const float* bo = (const float*)d_in[8];
    const float* qs = (const float*)d_in[9];
    const float* qb = (const float*)d_in[10];
    float* out = (float*)d_out;

    cudaFuncSetAttribute(lstm_seq, cudaFuncAttributeMaxDynamicSharedMemorySize, SMEM2);

    p1_gemm<<<dim3(G4 / 128, MROWS / 128), 256>>>(X, Wf, Wi, Wg, Wo, bf, bi, bg, bo);
    reset_k<<<1, 256>>>();
    lstm_seq<<<NCTA, 256, SMEM2>>>(Wf, Wi, Wg, Wo, qs, qb, out);
}

// round 15
// speedup vs baseline: 1.6257x; 1.0158x over previous
#include <cuda_runtime.h>
#include <cuda_bf16.h>
#include <cstdint>
#include <cstddef>

// Problem constants
#define T_STEPS 1024
#define BATCH   64
#define DIM     512
#define HID     512
#define DH      1024          // D + H
#define G4      2048          // 4*H
#define MROWS   (T_STEPS * BATCH)   // 65536

// Phase-2 partitioning: 4 groups x 32 CTAs, 1 CTA per SM
#define NGROUPS 4
#define CPG     32
#define NCTA    128
#define BPG     16            // batches per group
#define JPC     16            // hidden units per CTA
#define KPH     520           // padded h_s row stride (floats)

// ---------------- device scratch (static allocations only) ----------------
__device__ float    g_zx[(size_t)MROWS * G4];   // precomputed x-part + bias
__device__ float    g_h[2][BATCH][HID];         // double-buffered hidden state
__device__ unsigned g_cnt[NGROUPS * 32];        // barrier counters, 128B apart

__device__ __forceinline__ unsigned ld_acq(unsigned* p) {
    unsigned v;
    asm volatile("ld.acquire.gpu.u32 %0, [%1];" : "=r"(v) : "l"(p) : "memory");
    return v;
}

// ---------------- packed fp32 helpers (FFMA2 on sm_103) ----------------
__device__ __forceinline__ void fma2(unsigned long long& d, unsigned long long a,
                                     unsigned long long b) {
    asm("fma.rn.f32x2 %0, %1, %2, %0;" : "+l"(d) : "l"(a), "l"(b));
}
__device__ __forceinline__ unsigned long long pk2(float x, float y) {
    unsigned long long r;
    asm("mov.b64 %0, {%1, %2};" : "=l"(r) : "f"(x), "f"(y));
    return r;
}
__device__ __forceinline__ float2 unpk(unsigned long long v) {
    float2 r;
    asm("mov.b64 {%0, %1}, %2;" : "=f"(r.x), "=f"(r.y) : "l"(v));
    return r;
}

// ---------------- fast transcendentals (|.|-guarded, err ~1e-6) ----------------
__device__ __forceinline__ float fsig(float z) {
    float e = __expf(-fabsf(z));
    float r = __fdividef(1.f, 1.f + e);
    return z >= 0.f ? r : 1.f - r;
}
__device__ __forceinline__ float ftanh(float z) {
    float e = __expf(-2.f * fabsf(z));
    float r = __fdividef(1.f - e, 1.f + e);
    return copysignf(r, z);
}

// ---------------- cp.async helpers ----------------
__device__ __forceinline__ uint32_t smem_u32(const void* p) {
    uint32_t a;
    asm("{ .reg .u64 t; cvta.to.shared.u64 t, %1; cvt.u32.u64 %0, t; }" : "=r"(a) : "l"(p));
    return a;
}
__device__ __forceinline__ void cp16(uint32_t dst, const void* src) {
    asm volatile("cp.async.cg.shared.global [%0], [%1], 16;" :: "r"(dst), "l"(src));
}
__device__ __forceinline__ void cp_commit() { asm volatile("cp.async.commit_group;" ::: "memory"); }
__device__ __forceinline__ void cp_wait0() {
    asm volatile("cp.async.wait_group 0;" ::: "memory");
}

// =======================================================================
// Phase 1: fp32x2 SGEMM, tile 128x128, 8x8/thread.
// Smem PING-PONG: compute on buf cur while STS fills 1-cur and LDG
// prefetches 2 tiles ahead -> ONE sync per 16-k tile (was two).
// Inner k-step identical to the measured-best R6/R7 loop.
// =======================================================================
#define KPAD 132
__global__ __launch_bounds__(256, 2) void p1_gemm(
    const float* __restrict__ X,
    const float* __restrict__ Wf, const float* __restrict__ Wi,
    const float* __restrict__ Wg, const float* __restrict__ Wo,
    const float* __restrict__ bf, const float* __restrict__ bi,
    const float* __restrict__ bg, const float* __restrict__ bo)
{
    __shared__ float As[2][16][KPAD];
    __shared__ float Bs[2][16][KPAD];

    const int tid = threadIdx.x;
    const int m0  = blockIdx.y * 128;
    const int n0  = blockIdx.x * 128;
    const int gate = n0 >> 9;
    const float* Wsel = (gate == 0) ? Wf : (gate == 1) ? Wi : (gate == 2) ? Wg : Wo;
    const float* bsel = (gate == 0) ? bf : (gate == 1) ? bi : (gate == 2) ? bg : bo;
    const int jbase = n0 & 511;

    const int tm = tid & 15;
    const int tn = tid >> 4;
    const int lrow = tid >> 2, lkc = tid & 3;

    unsigned long long acc2[4][8];
#pragma unroll
    for (int i = 0; i < 4; i++)
#pragma unroll
        for (int q = 0; q < 8; q++) acc2[i][q] = 0ull;

    float4 ra[2], rb[2];
    auto ldg_tile = [&](int k0) {
#pragma unroll
        for (int l = 0; l < 2; l++) {
            int row = lrow + l * 64;
            ra[l] = *(const float4*)&X[(size_t)(m0 + row) * 512 + k0 + lkc * 4];
            rb[l] = *(const float4*)&Wsel[(size_t)(jbase + row) * DH + k0 + lkc * 4];
        }
    };
    auto sts_tile = [&](int buf) {
#pragma unroll
        for (int l = 0; l < 2; l++) {
            int row = lrow + l * 64;
            As[buf][lkc * 4 + 0][row] = ra[l].x;
            As[buf][lkc * 4 + 1][row] = ra[l].y;
            As[buf][lkc * 4 + 2][row] = ra[l].z;
            As[buf][lkc * 4 + 3][row] = ra[l].w;
            Bs[buf][lkc * 4 + 0][row] = rb[l].x;
            Bs[buf][lkc * 4 + 1][row] = rb[l].y;
            Bs[buf][lkc * 4 + 2][row] = rb[l].z;
            Bs[buf][lkc * 4 + 3][row] = rb[l].w;
        }
    };

    // prologue: tile 0 -> buf0 (smem), tile 1 -> regs
    ldg_tile(0);
    sts_tile(0);
    ldg_tile(16);
    __syncthreads();

    for (int it = 0; it < 32; it++) {
        const int cur = it & 1;
        // regs hold tile it+1: store it to the other buffer (overlaps compute)
        if (it + 1 < 32) sts_tile(1 - cur);
        // prefetch tile it+2 into regs (~2 compute blocks of latency cover)
        if (it + 2 < 32) ldg_tile((it + 2) * 16);

#pragma unroll
        for (int k = 0; k < 16; k++) {
            unsigned long long a2[4];
#pragma unroll
            for (int p = 0; p < 4; p++)
                a2[p] = *(const unsigned long long*)&As[cur][k][32 * p + 2 * tm];
            float4 bv0 = *(const float4*)&Bs[cur][k][tn * 8];
            float4 bv1 = *(const float4*)&Bs[cur][k][tn * 8 + 4];
            unsigned long long b2[8];
            b2[0] = pk2(bv0.x, bv0.x); b2[1] = pk2(bv0.y, bv0.y);
            b2[2] = pk2(bv0.z, bv0.z); b2[3] = pk2(bv0.w, bv0.w);
            b2[4] = pk2(bv1.x, bv1.x); b2[5] = pk2(bv1.y, bv1.y);
            b2[6] = pk2(bv1.z, bv1.z); b2[7] = pk2(bv1.w, bv1.w);
#pragma unroll
            for (int p = 0; p < 4; p++)
#pragma unroll
                for (int q = 0; q < 8; q++) fma2(acc2[p][q], a2[p], b2[q]);
        }
        __syncthreads();   // guards: cur fully read; 1-cur fully written
    }

    float bias[8];
#pragma unroll
    for (int q = 0; q < 8; q++) bias[q] = bsel[jbase + tn * 8 + q];

#pragma unroll
    for (int p = 0; p < 4; p++) {
        const int mrow = m0 + 32 * p + 2 * tm;
        float lo[8], hi[8];
#pragma unroll
        for (int q = 0; q < 8; q++) {
            float2 v = unpk(acc2[p][q]);
            lo[q] = v.x + bias[q];
            hi[q] = v.y + bias[q];
        }
        float* r0 = &g_zx[(size_t)mrow * G4 + n0 + tn * 8];
        float* r1 = r0 + G4;
        *(float4*)r0       = make_float4(lo[0], lo[1], lo[2], lo[3]);
        *(float4*)(r0 + 4) = make_float4(lo[4], lo[5], lo[6], lo[7]);
        *(float4*)r1       = make_float4(hi[0], hi[1], hi[2], hi[3]);
        *(float4*)(r1 + 4) = make_float4(hi[4], hi[5], hi[6], hi[7]);
    }
}

// =======================================================================
// Reset kernel
// =======================================================================
__global__ void reset_k()
{
    int tid = threadIdx.x;
    if (tid < NGROUPS * 32) g_cnt[tid] = 0;
    float* p = &g_h[0][0][0];
    for (int i = tid; i < BATCH * HID; i += 256) p[i] = 0.f;
}

// =======================================================================
// Phase 2: persistent sequential LSTM (R11 version VERBATIM — 5.31 ms;
// frozen after 9 failed restructure attempts).
// =======================================================================
#define SMEM2 ((32768 + 16 * KPH + 8192) * 4)

__global__ __launch_bounds__(256, 1) void lstm_seq(
    const float* __restrict__ Wf, const float* __restrict__ Wi,
    const float* __restrict__ Wg, const float* __restrict__ Wo,
    const float* __restrict__ q_scale, const float* __restrict__ q_bias,
    float* __restrict__ out)
{
    extern __shared__ float smf[];
    float* wp_s = smf;                                   // 32768 floats (128KB)
    float* h_s  = smf + 32768;                           // 16*KPH
    unsigned long long* red2 = (unsigned long long*)(smf + 32768 + 16 * KPH); // 4096 u64

    const int tid = threadIdx.x;
    const int cta = blockIdx.x;
    const int grp = cta >> 5;
    const int cig = cta & 31;
    const int b0  = grp * BPG;
    const int j0  = cig * JPC;

    // Load recurrent weights (columns [512,1024)) into paired+swizzled layout.
    for (int idx = tid; idx < 64 * 512; idx += 256) {
        int rr = idx >> 9, k = idx & 511;
        int gate = rr >> 4, jl_ = rr & 15;
        const float* wpt = (gate == 0) ? Wf : (gate == 1) ? Wi : (gate == 2) ? Wg : Wo;
        float v = wpt[(size_t)(j0 + jl_) * DH + 512 + k];
        int p = rr >> 1, half = rr & 1, g = k >> 1, ko = k & 1;
        wp_s[p * 1024 + ((g ^ (p & 7)) << 2) + ko * 2 + half] = v;
    }

    const int jl = tid & 15, bl = tid >> 4;
    const int j = j0 + jl, b = b0 + bl;
    const float qs = q_scale[j], qb = q_bias[j];

    const int lane = tid & 31, wrp = tid >> 5;
    const int rL = lane & 7, bL = lane >> 3;
    const int kbase = wrp * 64;
    const int uB = bl >> 2, bLL = bl & 3;
    const float* wthr = wp_s + rL * 1024;
    float* redf = (float*)red2;
    const uint32_t hs_base = smem_u32(h_s);
    unsigned* cntp = &g_cnt[grp * 32];

    float creg = 0.f;
    __syncthreads();

    for (int t = 0; t < T_STEPS; t++) {
        // ---- prefetch Zx operand for this (t, b, j) early (DRAM latency) ----
        const float* zxp = &g_zx[((size_t)(t * BATCH + b)) * G4 + j];
        float zpre[4];
#pragma unroll
        for (int gate = 0; gate < 4; gate++) zpre[gate] = __ldcg(zxp + gate * 512);

        // ---- stage h_t for this group's 16 batches (L2 -> smem, cp.async) ----
        const float* hsrc = &g_h[t & 1][b0][0];
#pragma unroll
        for (int l = 0; l < 8; l++) {
            int i = tid + l * 256;
            int row = i >> 7, c4 = i & 127;
            cp16(hs_base + (uint32_t)(row * KPH + c4 * 4) * 4u, hsrc + row * 512 + c4 * 4);
        }
        cp_commit();
        cp_wait0();
        __syncthreads();

        // ---- packed GEMM: warp owns K-chunk of 64; 16 batch x 8 row-pairs ----
        unsigned long long acc2[4][4];
#pragma unroll
        for (int u = 0; u < 4; u++)
#pragma unroll
            for (int jj = 0; jj < 4; jj++) acc2[u][jj] = 0ull;

#pragma unroll 4
        for (int kk = 0; kk < 64; kk += 4) {
            const int k = kbase + kk;
            const int g0 = k >> 1;                       // even
            const int s0 = ((g0 ^ rL) << 2);
            const int s1 = (((g0 + 1) ^ rL) << 2);

            unsigned long long hp[4][4];
#pragma unroll
            for (int u = 0; u < 4; u++) {
                float4 hv = *(const float4*)&h_s[(bL + 4 * u) * KPH + k];
                hp[u][0] = pk2(hv.x, hv.x);
                hp[u][1] = pk2(hv.y, hv.y);
                hp[u][2] = pk2(hv.z, hv.z);
                hp[u][3] = pk2(hv.w, hv.w);
            }
#pragma unroll
            for (int jj = 0; jj < 4; jj++) {
                const float* wj = wthr + jj * 8192;
                ulonglong2 wA = *(const ulonglong2*)(wj + s0);   // k, k+1
                ulonglong2 wB = *(const ulonglong2*)(wj + s1);   // k+2, k+3
#pragma unroll
                for (int u = 0; u < 4; u++) {
                    fma2(acc2[u][jj], hp[u][0], wA.x);
                    fma2(acc2[u][jj], hp[u][1], wA.y);
                    fma2(acc2[u][jj], hp[u][2], wB.x);
                    fma2(acc2[u][jj], hp[u][3], wB.y);
                }
            }
        }

        // ---- write packed partials ----
#pragma unroll
        for (int u = 0; u < 4; u++)
#pragma unroll
            for (int jj = 0; jj < 4; jj++)
                red2[wrp * 512 + (u * 4 + jj) * 32 + rL * 4 + bL] = acc2[u][jj];
        __syncthreads();

        // ---- reduce across 8 warps, add Zx, gates, state update ----
        float z[4];
#pragma unroll
        for (int gate = 0; gate < 4; gate++) {
            int r = gate * 16 + jl;
            int p = r >> 1;
            int idx = ((uB * 4 + (p >> 3)) * 32 + (p & 7) * 4 + bLL) * 2 + (r & 1);
            float s = 0.f;
#pragma unroll
            for (int ww = 0; ww < 8; ww++) s += redf[ww * 1024 + idx];
            z[gate] = s + zpre[gate];
        }

        float fg = ftanh(fsig(z[0]) * qs + qb);
        float ig = ftanh(fsig(z[1]) * qs + qb);
        float gg = ftanh(ftanh(z[2]) * qs + qb);
        float og = ftanh(fsig(z[3]) * qs + qb);

        float c = fg * creg + ig * gg;
        creg = c;
        float h = og * ftanh(c);

        g_h[(t + 1) & 1][b][j] = h;
        __syncthreads();              // all h stores done CTA-wide

        // arrive early: overlap out[] stores with peers' arrivals
        if (t < T_STEPS - 1 && tid == 0) {
            __threadfence();
            atomicAdd(cntp, 1u);
        }

        out[(size_t)t * (BATCH * HID) + b * HID + j] = h;
        if (t == T_STEPS - 1) {
            out[(size_t)T_STEPS * (BATCH * HID) + b * HID + j] = h;                 // hx
            out[(size_t)T_STEPS * (BATCH * HID) + BATCH * HID + b * HID + j] = c;   // cx
        }

        if (t < T_STEPS - 1) {
            if (tid == 0) {
                const unsigned target = (unsigned)(t + 1) * CPG;
                while (ld_acq(cntp) < target) { __nanosleep(16); }
            }
            __syncthreads();
        }
    }
}

// =======================================================================
// Launch (sequential, single stream)
// =======================================================================
extern "C" void kernel_launch(void* const* d_in, const int* in_sizes, int n_in,
                              void* d_out, int out_size)
{
    const float* X  = (const float*)d_in[0];
    const float* Wf = (const float*)d_in[1];
    const float* bf = (const float*)d_in[2];
    const float* Wi = (const float*)d_in[3];
    const float* bi = (const float*)d_in[4];
    const float* Wg = (const float*)d_in[5];
    const float* bg = (const float*)d_in[6];
    const float* Wo = (const float*)d_in[7];
    const float* bo = (const float*)d_in[8];
    const float* qs = (const float*)d_in[9];
    const float* qb = (const float*)d_in[10];
    float* out = (float*)d_out;

    cudaFuncSetAttribute(lstm_seq, cudaFuncAttributeMaxDynamicSharedMemorySize, SMEM2);

    p1_gemm<<<dim3(G4 / 128, MROWS / 128), 256>>>(X, Wf, Wi, Wg, Wo, bf, bi, bg, bo);
    reset_k<<<1, 256>>>();
    lstm_seq<<<NCTA, 256, SMEM2>>>(Wf, Wi, Wg, Wo, qs, qb, out);
}